// round 12
// baseline (speedup 1.0000x reference)
#include <cuda_runtime.h>
#include <cuda_fp16.h>
#include <cstdint>

// ---------------------------------------------------------------------------
// Problem constants
// ---------------------------------------------------------------------------
#define Bsz  8
#define Sq   4096
#define Ltxt 77
#define Limg 16
#define Dm   1280
#define Cm   2048
#define Hh   20
#define DHd  64
#define Mbig (Bsz * Sq)          // 32768
#define Mtxt (Bsz * Ltxt)        // 616
#define Mimg (Bsz * Limg)        // 128

// ---------------------------------------------------------------------------
// Scratch (__device__ globals; no allocation allowed)
// ---------------------------------------------------------------------------
__device__ __half g_A16[(size_t)Mbig * Dm];
__device__ __half g_O16[(size_t)Mbig * Dm];
__device__ __half g_T16[(size_t)Mtxt * Cm];
__device__ __half g_I16[(size_t)Mimg * Cm];
__device__ __half g_H16[(size_t)Mimg * Cm];

// Q and K/V as fp16 hi/lo (attention runs 3-pass)
__device__ __half g_Qhi[(size_t)Mbig * Dm], g_Qlo[(size_t)Mbig * Dm];
// z: 0 Ktxt, 1 Vtxt, 2 Kid, 3 Vid, 4 Khair, 5 Vhair
__device__ __half g_KVhi[6][(size_t)Mtxt * Dm];
__device__ __half g_KVlo[6][(size_t)Mtxt * Dm];

// transposed + split weights: Wt[n][k] fp16 hi/lo (B operands)
__device__ __half g_WtQ_hi[Dm * Dm],  g_WtQ_lo[Dm * Dm];
__device__ __half g_WtO_hi[Dm * Dm],  g_WtO_lo[Dm * Dm];
__device__ __half g_WtKV_hi[6][(size_t)Dm * Cm];
__device__ __half g_WtKV_lo[6][(size_t)Dm * Cm];

// ---------------------------------------------------------------------------
// Helpers
// ---------------------------------------------------------------------------
__device__ __forceinline__ uint32_t smem_u32(const void* p) {
    uint32_t a;
    asm("{ .reg .u64 t; cvta.to.shared.u64 t, %1; cvt.u32.u64 %0, t; }"
        : "=r"(a) : "l"(p));
    return a;
}
__device__ __forceinline__ void split1h(float v, __half& h, __half& l) {
    h = __float2half_rn(v);
    l = __float2half_rn(v - __half2float(h));
}
__device__ __forceinline__ void sp2h(float v0, float v1, uint32_t& h, uint32_t& l) {
    __half b0 = __float2half_rn(v0);
    __half b1 = __float2half_rn(v1);
    __half2 hh = __halves2half2(b0, b1);
    h = *(uint32_t*)&hh;
    __half2 ll = __halves2half2(
        __float2half_rn(v0 - __half2float(b0)),
        __float2half_rn(v1 - __half2float(b1)));
    l = *(uint32_t*)&ll;
}
__device__ __forceinline__ uint32_t pk2h(float v0, float v1) {
    __half2 hh = __halves2half2(__float2half_rn(v0), __float2half_rn(v1));
    return *(uint32_t*)&hh;
}
__device__ __forceinline__ void cpa16(uint32_t dst, const void* src, bool p) {
    int sz = p ? 16 : 0;
    asm volatile("cp.async.cg.shared.global [%0], [%1], 16, %2;"
                 :: "r"(dst), "l"(src), "r"(sz));
}
__device__ __forceinline__ void ldm4(uint32_t* r, uint32_t addr) {
    asm volatile("ldmatrix.sync.aligned.m8n8.x4.shared.b16 {%0,%1,%2,%3}, [%4];"
                 : "=r"(r[0]), "=r"(r[1]), "=r"(r[2]), "=r"(r[3]) : "r"(addr));
}
__device__ __forceinline__ void ldm4t(uint32_t* r, uint32_t addr) {
    asm volatile("ldmatrix.sync.aligned.m8n8.x4.trans.shared.b16 {%0,%1,%2,%3}, [%4];"
                 : "=r"(r[0]), "=r"(r[1]), "=r"(r[2]), "=r"(r[3]) : "r"(addr));
}
__device__ __forceinline__ void mma16816(float* d, const uint32_t* a,
                                         uint32_t b0, uint32_t b1) {
    asm volatile(
        "mma.sync.aligned.m16n8k16.row.col.f32.f16.f16.f32 "
        "{%0,%1,%2,%3}, {%4,%5,%6,%7}, {%8,%9}, {%0,%1,%2,%3};"
        : "+f"(d[0]), "+f"(d[1]), "+f"(d[2]), "+f"(d[3])
        : "r"(a[0]), "r"(a[1]), "r"(a[2]), "r"(a[3]), "r"(b0), "r"(b1));
}

// ---------------------------------------------------------------------------
// Weight transpose + split:  W[K,N=1280] fp32  ->  Wt_hi/lo[N,K] fp16
// ---------------------------------------------------------------------------
__global__ void __launch_bounds__(256)
transpose_split_kernel(const float* __restrict__ Wq, const float* __restrict__ Wo,
                       const float* __restrict__ Wk,  const float* __restrict__ Wv,
                       const float* __restrict__ Wki, const float* __restrict__ Wvi,
                       const float* __restrict__ Wkh, const float* __restrict__ Wvh) {
    const float* W; __half* Hi; __half* Lo; int K;
    switch (blockIdx.z) {
        case 0: W = Wq;  Hi = g_WtQ_hi;     Lo = g_WtQ_lo;     K = Dm; break;
        case 1: W = Wo;  Hi = g_WtO_hi;     Lo = g_WtO_lo;     K = Dm; break;
        case 2: W = Wk;  Hi = g_WtKV_hi[0]; Lo = g_WtKV_lo[0]; K = Cm; break;
        case 3: W = Wv;  Hi = g_WtKV_hi[1]; Lo = g_WtKV_lo[1]; K = Cm; break;
        case 4: W = Wki; Hi = g_WtKV_hi[2]; Lo = g_WtKV_lo[2]; K = Cm; break;
        case 5: W = Wvi; Hi = g_WtKV_hi[3]; Lo = g_WtKV_lo[3]; K = Cm; break;
        case 6: W = Wkh; Hi = g_WtKV_hi[4]; Lo = g_WtKV_lo[4]; K = Cm; break;
        default:W = Wvh; Hi = g_WtKV_hi[5]; Lo = g_WtKV_lo[5]; K = Cm; break;
    }
    int k0 = blockIdx.y * 32;
    if (k0 >= K) return;
    int n0 = blockIdx.x * 32;

    __shared__ float ts[32][33];
    int tx = threadIdx.x & 31;
    int ty = threadIdx.x >> 5;
#pragma unroll
    for (int j = 0; j < 4; j++)
        ts[ty + j * 8][tx] = W[(size_t)(k0 + ty + j * 8) * Dm + n0 + tx];
    __syncthreads();
#pragma unroll
    for (int j = 0; j < 4; j++) {
        int nn = ty + j * 8;
        __half h, l;
        split1h(ts[tx][nn], h, l);
        size_t off = (size_t)(n0 + nn) * K + k0 + tx;
        Hi[off] = h;
        Lo[off] = l;
    }
}

// ---------------------------------------------------------------------------
// Activation convert: fp32 -> single fp16
// ---------------------------------------------------------------------------
__global__ void __launch_bounds__(256)
split_inputs_kernel(const float* __restrict__ hidden, const float* __restrict__ text,
                    const float* __restrict__ ids,    const float* __restrict__ hair) {
    const float* src; __half* o16; size_t n;
    switch (blockIdx.z) {
        case 0:  src = hidden; o16 = g_A16; n = (size_t)Mbig * Dm; break;
        case 1:  src = text;   o16 = g_T16; n = (size_t)Mtxt * Cm; break;
        case 2:  src = ids;    o16 = g_I16; n = (size_t)Mimg * Cm; break;
        default: src = hair;   o16 = g_H16; n = (size_t)Mimg * Cm; break;
    }
    size_t n4 = n >> 2;
    for (size_t i = (size_t)blockIdx.x * 256 + threadIdx.x; i < n4;
         i += (size_t)gridDim.x * 256) {
        float4 v = ((const float4*)src)[i];
        uint2 hp;
        hp.x = pk2h(v.x, v.y);
        hp.y = pk2h(v.z, v.w);
        *(uint2*)(o16 + i * 4) = hp;
    }
}

// ---------------------------------------------------------------------------
// Warp-MMA fp16 2-pass GEMM, 3-stage cp.async pipeline (latency cover).
// 128x128 tile, BK=32, 8 warps (64x32 each).
// ---------------------------------------------------------------------------
#define BM 128
#define BN 128
#define BKB 32
#define ROWB 80
#define A_S  0
#define B_HI 10240
#define B_LO 20480
#define STAGE_B 30720
#define NSTAGE 3
#define GSMEM (NSTAGE * STAGE_B)

__device__ __forceinline__ void mma_gemm_body(
    const __half* __restrict__ A16,
    const __half* __restrict__ Bhi, const __half* __restrict__ Blo,
    const float* __restrict__ bias,
    float* __restrict__ Cf,
    __half* __restrict__ Chi, __half* __restrict__ Clo,
    int M, int K, int bx, int by)
{
    extern __shared__ __align__(128) char smem[];
    const int tid  = threadIdx.x;
    const int lane = tid & 31;
    const int wid  = tid >> 5;
    const int wm   = wid & 1;
    const int wn   = wid >> 1;
    const int row0 = by * BM;
    const int col0 = bx * BN;
    const int nch  = K / BKB;

    float acc[4][4][4];
#pragma unroll
    for (int a = 0; a < 4; a++)
#pragma unroll
        for (int b = 0; b < 4; b++)
#pragma unroll
            for (int d = 0; d < 4; d++) acc[a][b][d] = 0.f;

    auto ld_stage = [&](int c, int s) {
        uint32_t base = smem_u32(smem + s * STAGE_B);
        int k0 = c * BKB;
#pragma unroll
        for (int i = 0; i < 2; i++) {
            int lin = i * 256 + tid;
            int r   = lin >> 2;
            int sg  = lin & 3;
            uint32_t d = base + r * ROWB + sg * 16;
            int grow = row0 + r;
            bool p = grow < M;
            int ga = p ? grow : (M - 1);
            size_t aoff = (size_t)ga * K + k0 + sg * 8;
            cpa16(d + A_S, A16 + aoff, p);
            size_t boff = (size_t)(col0 + r) * K + k0 + sg * 8;
            cpa16(d + B_HI, Bhi + boff, true);
            cpa16(d + B_LO, Blo + boff, true);
        }
        asm volatile("cp.async.commit_group;" ::: "memory");
    };

    auto compute = [&](int s) {
        uint32_t sb = smem_u32(smem + s * STAGE_B);
        uint32_t aB = sb + A_S + (wm * 64) * ROWB;
        uint32_t bB = sb + B_HI + (wn * 32) * ROWB;
        uint32_t lrow  = lane & 15;
        uint32_t lhalf = (lane >> 4) * 16;
#pragma unroll
        for (int ks = 0; ks < 2; ks++) {
            uint32_t bh[2][4], bl[2][4];
#pragma unroll
            for (int ng = 0; ng < 2; ng++) {
                uint32_t ad = bB + (ng * 16 + lrow) * ROWB + ks * 32 + lhalf;
                ldm4(bh[ng], ad);
                ldm4(bl[ng], ad + (B_LO - B_HI));
            }
#pragma unroll
            for (int mt = 0; mt < 4; mt++) {
                uint32_t a[4];
                uint32_t ad = aB + (mt * 16 + lrow) * ROWB + ks * 32 + lhalf;
                ldm4(a, ad);
#pragma unroll
                for (int j = 0; j < 4; j++) {
                    int ng = j >> 1, q = j & 1;
                    mma16816(acc[mt][j], a, bh[ng][q], bh[ng][q + 2]);
                    mma16816(acc[mt][j], a, bl[ng][q], bl[ng][q + 2]);
                }
            }
        }
    };

    // prime 2 stages
    ld_stage(0, 0);
    if (nch > 1) ld_stage(1, 1);

    for (int c = 0; c < nch; c++) {
        int s = c % NSTAGE;
        if (c + 2 < nch) {
            ld_stage(c + 2, (c + 2) % NSTAGE);
            asm volatile("cp.async.wait_group 2;" ::: "memory");
        } else if (c + 1 < nch) {
            asm volatile("cp.async.wait_group 1;" ::: "memory");
        } else {
            asm volatile("cp.async.wait_group 0;" ::: "memory");
        }
        __syncthreads();
        compute(s);
        __syncthreads();
    }

    const int tg = lane >> 2, tq = lane & 3;
#pragma unroll
    for (int mt = 0; mt < 4; mt++) {
        int r0 = row0 + wm * 64 + mt * 16 + tg;
        int r1 = r0 + 8;
#pragma unroll
        for (int j = 0; j < 4; j++) {
            int col = col0 + wn * 32 + j * 8 + tq * 2;
            if (Cf) {
                float b0 = 0.f, b1 = 0.f;
                if (bias) { b0 = bias[col]; b1 = bias[col + 1]; }
                if (r0 < M)
                    *(float2*)(Cf + (size_t)r0 * Dm + col) =
                        make_float2(acc[mt][j][0] + b0, acc[mt][j][1] + b1);
                if (r1 < M)
                    *(float2*)(Cf + (size_t)r1 * Dm + col) =
                        make_float2(acc[mt][j][2] + b0, acc[mt][j][3] + b1);
            } else {
                uint32_t h, l;
                if (r0 < M) {
                    sp2h(acc[mt][j][0], acc[mt][j][1], h, l);
                    *(uint32_t*)(Chi + (size_t)r0 * Dm + col) = h;
                    *(uint32_t*)(Clo + (size_t)r0 * Dm + col) = l;
                }
                if (r1 < M) {
                    sp2h(acc[mt][j][2], acc[mt][j][3], h, l);
                    *(uint32_t*)(Chi + (size_t)r1 * Dm + col) = h;
                    *(uint32_t*)(Clo + (size_t)r1 * Dm + col) = l;
                }
            }
        }
    }
}

// Merged Q + 6xKV GEMM (split fp16 outputs for attention 3-pass)
__global__ void __launch_bounds__(256, 2)
gemm_qkv_kernel() {
    int y = blockIdx.y;
    if (y < 256) {
        mma_gemm_body(g_A16, g_WtQ_hi, g_WtQ_lo, nullptr,
                      nullptr, g_Qhi, g_Qlo, Mbig, Dm, blockIdx.x, y);
        return;
    }
    int yy = y - 256;
    const __half* a16; int M, z, by;
    if (yy < 5)       { z = 0; by = yy;     a16 = g_T16; M = Mtxt; }
    else if (yy < 10) { z = 1; by = yy - 5; a16 = g_T16; M = Mtxt; }
    else if (yy == 10){ z = 2; by = 0;      a16 = g_I16; M = Mimg; }
    else if (yy == 11){ z = 3; by = 0;      a16 = g_I16; M = Mimg; }
    else if (yy == 12){ z = 4; by = 0;      a16 = g_H16; M = Mimg; }
    else              { z = 5; by = 0;      a16 = g_H16; M = Mimg; }
    mma_gemm_body(a16, g_WtKV_hi[z], g_WtKV_lo[z], nullptr,
                  nullptr, g_KVhi[z], g_KVlo[z], M, Cm, blockIdx.x, by);
}

__global__ void __launch_bounds__(256, 2)
gemm_out_kernel(const float* __restrict__ bo, float* __restrict__ out) {
    mma_gemm_body(g_O16, g_WtO_hi, g_WtO_lo, bo,
                  out, nullptr, nullptr, Mbig, Dm, blockIdx.x, blockIdx.y);
}

// ---------------------------------------------------------------------------
// Flash-style MMA attention (fp16, 3-pass QK/PV). Block = 128 q x one (b,h).
// ---------------------------------------------------------------------------
#define AT_QHI 0
#define AT_QLO 18432
#define AT_KHI 36864
#define AT_KLO 48384
#define AT_SMEM 59904
#define KROW 144

__global__ void __launch_bounds__(256) attn_kernel() {
    extern __shared__ __align__(128) char sm[];
    const int tid  = threadIdx.x;
    const int lane = tid & 31;
    const int wid  = tid >> 5;
    const int lrow = lane & 15;
    const int lhalf = (lane >> 4) * 16;
    const int tg = lane >> 2;
    const int tq = lane & 3;
    const int q0 = blockIdx.x * 128;
    const int b  = blockIdx.y / Hh;
    const int hd = blockIdx.y % Hh;
    const int wq0 = wid * 16;

    const uint32_t smb = smem_u32(sm);

    for (int i = tid; i < 1024; i += 256) {
        int row = i >> 3, seg = i & 7;
        size_t off = ((size_t)(b * Sq + q0 + row)) * Dm + hd * 64 + seg * 8;
        *(uint4*)(sm + AT_QHI + row * KROW + seg * 16) = *(const uint4*)(g_Qhi + off);
        *(uint4*)(sm + AT_QLO + row * KROW + seg * 16) = *(const uint4*)(g_Qlo + off);
    }
    __syncthreads();

    uint32_t qh[4][4], ql[4][4];
#pragma unroll
    for (int ks = 0; ks < 4; ks++) {
        uint32_t ad = smb + AT_QHI + (wq0 + lrow) * KROW + ks * 32 + lhalf;
        ldm4(qh[ks], ad);
        ldm4(ql[ks], ad + (AT_QLO - AT_QHI));
    }

    float O[8][4];
#pragma unroll
    for (int i = 0; i < 8; i++)
#pragma unroll
        for (int e = 0; e < 4; e++) O[i][e] = 0.f;

    // ======================= branch 0: text (77 j, pad 80) =======================
    {
        for (int i = tid; i < 640; i += 256) {
            int row = i >> 3, seg = i & 7;
            uint4 vh = make_uint4(0, 0, 0, 0), vl = vh;
            if (row < Ltxt) {
                size_t off = ((size_t)(b * Ltxt + row)) * Dm + hd * 64 + seg * 8;
                vh = *(const uint4*)(g_KVhi[0] + off);
                vl = *(const uint4*)(g_KVlo[0] + off);
            }
            *(uint4*)(sm + AT_KHI + row * KROW + seg * 16) = vh;
            *(uint4*)(sm + AT_KLO + row * KROW + seg * 16) = vl;
        }
        __syncthreads();

        float S[10][4];
#pragma unroll
        for (int t = 0; t < 10; t++)
#pragma unroll
            for (int e = 0; e < 4; e++) S[t][e] = 0.f;

#pragma unroll
        for (int np = 0; np < 5; np++)
#pragma unroll
            for (int ks = 0; ks < 4; ks++) {
                uint32_t bh[4], bl[4];
                uint32_t ad = smb + AT_KHI + (np * 16 + lrow) * KROW + ks * 32 + lhalf;
                ldm4(bh, ad);
                ldm4(bl, ad + (AT_KLO - AT_KHI));
#pragma unroll
                for (int q = 0; q < 2; q++) {
                    int t = np * 2 + q;
                    mma16816(S[t], qh[ks], bh[q], bh[q + 2]);
                    mma16816(S[t], qh[ks], bl[q], bl[q + 2]);
                    mma16816(S[t], ql[ks], bh[q], bh[q + 2]);
                }
            }

#pragma unroll
        for (int t = 0; t < 10; t++)
#pragma unroll
            for (int e = 0; e < 4; e++) S[t][e] *= 0.125f;
        if (tq == 3) { S[9][0] = -1e30f; S[9][2] = -1e30f; }
        if (tq >= 2) { S[9][1] = -1e30f; S[9][3] = -1e30f; }

        float mx0 = -1e30f, mx1 = -1e30f;
#pragma unroll
        for (int t = 0; t < 10; t++) {
            mx0 = fmaxf(mx0, fmaxf(S[t][0], S[t][1]));
            mx1 = fmaxf(mx1, fmaxf(S[t][2], S[t][3]));
        }
        mx0 = fmaxf(mx0, __shfl_xor_sync(0xffffffffu, mx0, 1));
        mx0 = fmaxf(mx0, __shfl_xor_sync(0xffffffffu, mx0, 2));
        mx1 = fmaxf(mx1, __shfl_xor_sync(0xffffffffu, mx1, 1));
        mx1 = fmaxf(mx1, __shfl_xor_sync(0xffffffffu, mx1, 2));
        float s0 = 0.f, s1 = 0.f;
#pragma unroll
        for (int t = 0; t < 10; t++) {
            S[t][0] = __expf(S[t][0] - mx0); S[t][1] = __expf(S[t][1] - mx0);
            S[t][2] = __expf(S[t][2] - mx1); S[t][3] = __expf(S[t][3] - mx1);
            s0 += S[t][0] + S[t][1];
            s1 += S[t][2] + S[t][3];
        }
        s0 += __shfl_xor_sync(0xffffffffu, s0, 1);
        s0 += __shfl_xor_sync(0xffffffffu, s0, 2);
        s1 += __shfl_xor_sync(0xffffffffu, s1, 1);
        s1 += __shfl_xor_sync(0xffffffffu, s1, 2);
        float inv0 = 1.f / s0, inv1 = 1.f / s1;

        uint32_t phi[5][4], plo[5][4];
#pragma unroll
        for (int kj = 0; kj < 5; kj++) {
            int t0 = 2 * kj, t1 = 2 * kj + 1;
            sp2h(S[t0][0] * inv0, S[t0][1] * inv0, phi[kj][0], plo[kj][0]);
            sp2h(S[t0][2] * inv1, S[t0][3] * inv1, phi[kj][1], plo[kj][1]);
            sp2h(S[t1][0] * inv0, S[t1][1] * inv0, phi[kj][2], plo[kj][2]);
            sp2h(S[t1][2] * inv1, S[t1][3] * inv1, phi[kj][3], plo[kj][3]);
        }
        __syncthreads();

        for (int i = tid; i < 640; i += 256) {
            int row = i >> 3, seg = i & 7;
            uint4 vh = make_uint4(0, 0, 0, 0), vl = vh;
            if (row < Ltxt) {
                size_t off = ((size_t)(b * Ltxt + row)) * Dm + hd * 64 + seg * 8;
                vh = *(const uint4*)(g_KVhi[1] + off);
                vl = *(const uint4*)(g_KVlo[1] + off);
            }
            *(uint4*)(sm + AT_KHI + row * KROW + seg * 16) = vh;
            *(uint4*)(sm + AT_KLO + row * KROW + seg * 16) = vl;
        }
        __syncthreads();

#pragma unroll
        for (int kj = 0; kj < 5; kj++) {
            int vrow = kj * 16 + ((lane >> 3) & 1) * 8 + (lane & 7);
#pragma unroll
            for (int ndp = 0; ndp < 4; ndp++) {
                uint32_t vh[4], vl[4];
                uint32_t ad = smb + AT_KHI + vrow * KROW +
                              (ndp * 2 + (lane >> 4)) * 16;
                ldm4t(vh, ad);
                ldm4t(vl, ad + (AT_KLO - AT_KHI));
                mma16816(O[ndp * 2],     phi[kj], vh[0], vh[1]);
                mma16816(O[ndp * 2],     phi[kj], vl[0], vl[1]);
                mma16816(O[ndp * 2],     plo[kj], vh[0], vh[1]);
                mma16816(O[ndp * 2 + 1], phi[kj], vh[2], vh[3]);
                mma16816(O[ndp * 2 + 1], phi[kj], vl[2], vl[3]);
                mma16816(O[ndp * 2 + 1], plo[kj], vh[2], vh[3]);
            }
        }
        __syncthreads();
    }

    // =============== branch 1: merged id (j 0-15) | hair (j 16-31) ===============
    {
        {
            int i = tid;
            int row = i >> 3, seg = i & 7;
            int src_z = (row < 16) ? 2 : 4;
            int r = (row < 16) ? row : row - 16;
            size_t off = ((size_t)(b * Limg + r)) * Dm + hd * 64 + seg * 8;
            *(uint4*)(sm + AT_KHI + row * KROW + seg * 16) =
                *(const uint4*)(g_KVhi[src_z] + off);
            *(uint4*)(sm + AT_KLO + row * KROW + seg * 16) =
                *(const uint4*)(g_KVlo[src_z] + off);
        }
        __syncthreads();

        float S[4][4];
#pragma unroll
        for (int t = 0; t < 4; t++)
#pragma unroll
            for (int e = 0; e < 4; e++) S[t][e] = 0.f;

#pragma unroll
        for (int np = 0; np < 2; np++)
#pragma unroll
            for (int ks = 0; ks < 4; ks++) {
                uint32_t bh[4], bl[4];
                uint32_t ad = smb + AT_KHI + (np * 16 + lrow) * KROW + ks * 32 + lhalf;
                ldm4(bh, ad);
                ldm4(bl, ad + (AT_KLO - AT_KHI));
#pragma unroll
                for (int q = 0; q < 2; q++) {
                    int t = np * 2 + q;
                    mma16816(S[t], qh[ks], bh[q], bh[q + 2]);
                    mma16816(S[t], qh[ks], bl[q], bl[q + 2]);
                    mma16816(S[t], ql[ks], bh[q], bh[q + 2]);
                }
            }

#pragma unroll
        for (int t = 0; t < 4; t++)
#pragma unroll
            for (int e = 0; e < 4; e++) S[t][e] *= 0.125f;

        uint32_t phi[2][4], plo[2][4];
#pragma unroll
        for (int hf = 0; hf < 2; hf++) {
            int ta = 2 * hf, tb = 2 * hf + 1;
            float mx0 = fmaxf(fmaxf(S[ta][0], S[ta][1]), fmaxf(S[tb][0], S[tb][1]));
            float mx1 = fmaxf(fmaxf(S[ta][2], S[ta][3]), fmaxf(S[tb][2], S[tb][3]));
            mx0 = fmaxf(mx0, __shfl_xor_sync(0xffffffffu, mx0, 1));
            mx0 = fmaxf(mx0, __shfl_xor_sync(0xffffffffu, mx0, 2));
            mx1 = fmaxf(mx1, __shfl_xor_sync(0xffffffffu, mx1, 1));
            mx1 = fmaxf(mx1, __shfl_xor_sync(0xffffffffu, mx1, 2));
            float e00 = __expf(S[ta][0] - mx0), e01 = __expf(S[ta][1] - mx0);
            float e02 = __expf(S[ta][2] - mx1), e03 = __expf(S[ta][3] - mx1);
            float e10 = __expf(S[tb][0] - mx0), e11 = __expf(S[tb][1] - mx0);
            float e12 = __expf(S[tb][2] - mx1), e13 = __expf(S[tb][3] - mx1);
            float s0 = e00 + e01 + e10 + e11;
            float s1 = e02 + e03 + e12 + e13;
            s0 += __shfl_xor_sync(0xffffffffu, s0, 1);
            s0 += __shfl_xor_sync(0xffffffffu, s0, 2);
            s1 += __shfl_xor_sync(0xffffffffu, s1, 1);
            s1 += __shfl_xor_sync(0xffffffffu, s1, 2);
            float inv0 = 1.f / s0, inv1 = 1.f / s1;
            sp2h(e00 * inv0, e01 * inv0, phi[hf][0], plo[hf][0]);
            sp2h(e02 * inv1, e03 * inv1, phi[hf][1], plo[hf][1]);
            sp2h(e10 * inv0, e11 * inv0, phi[hf][2], plo[hf][2]);
            sp2h(e12 * inv1, e13 * inv1, phi[hf][3], plo[hf][3]);
        }
        __syncthreads();

        {
            int i = tid;
            int row = i >> 3, seg = i & 7;
            int src_z = (row < 16) ? 3 : 5;
            int r = (row < 16) ? row : row - 16;
            size_t off = ((size_t)(b * Limg + r)) * Dm + hd * 64 + seg * 8;
            *(uint4*)(sm + AT_KHI + row * KROW + seg * 16) =
                *(const uint4*)(g_KVhi[src_z] + off);
            *(uint4*)(sm + AT_KLO + row * KROW + seg * 16) =
                *(const uint4*)(g_KVlo[src_z] + off);
        }
        __syncthreads();

#pragma unroll
        for (int kj = 0; kj < 2; kj++) {
            int vrow = kj * 16 + ((lane >> 3) & 1) * 8 + (lane & 7);
#pragma unroll
            for (int ndp = 0; ndp < 4; ndp++) {
                uint32_t vh[4], vl[4];
                uint32_t ad = smb + AT_KHI + vrow * KROW +
                              (ndp * 2 + (lane >> 4)) * 16;
                ldm4t(vh, ad);
                ldm4t(vl, ad + (AT_KLO - AT_KHI));
                mma16816(O[ndp * 2],     phi[kj], vh[0], vh[1]);
                mma16816(O[ndp * 2],     phi[kj], vl[0], vl[1]);
                mma16816(O[ndp * 2],     plo[kj], vh[0], vh[1]);
                mma16816(O[ndp * 2 + 1], phi[kj], vh[2], vh[3]);
                mma16816(O[ndp * 2 + 1], phi[kj], vl[2], vl[3]);
                mma16816(O[ndp * 2 + 1], plo[kj], vh[2], vh[3]);
            }
        }
    }

    // ---- epilogue: single-fp16 O (out-GEMM A operand, 2-pass) ----
    {
        size_t r0 = (size_t)(b * Sq + q0 + wq0 + tg) * Dm + hd * 64 + tq * 2;
        size_t r1 = r0 + 8 * (size_t)Dm;
#pragma unroll
        for (int nd = 0; nd < 8; nd++) {
            *(uint32_t*)(g_O16 + r0 + nd * 8) = pk2h(O[nd][0], O[nd][1]);
            *(uint32_t*)(g_O16 + r1 + nd * 8) = pk2h(O[nd][2], O[nd][3]);
        }
    }
}

// ---------------------------------------------------------------------------
// kernel_launch
// ---------------------------------------------------------------------------
extern "C" void kernel_launch(void* const* d_in, const int* in_sizes, int n_in,
                              void* d_out, int out_size) {
    const float* hidden = (const float*)d_in[0];
    const float* text   = (const float*)d_in[1];
    const float* ids    = (const float*)d_in[2];
    const float* hair   = (const float*)d_in[3];
    const float* Wq     = (const float*)d_in[4];
    const float* Wk     = (const float*)d_in[5];
    const float* Wv     = (const float*)d_in[6];
    const float* Wo     = (const float*)d_in[7];
    const float* bo     = (const float*)d_in[8];
    const float* Wk_id  = (const float*)d_in[9];
    const float* Wv_id  = (const float*)d_in[10];
    const float* Wk_h   = (const float*)d_in[11];
    const float* Wv_h   = (const float*)d_in[12];
    float* out = (float*)d_out;

    cudaFuncSetAttribute(gemm_qkv_kernel, cudaFuncAttributeMaxDynamicSharedMemorySize, GSMEM);
    cudaFuncSetAttribute(gemm_out_kernel, cudaFuncAttributeMaxDynamicSharedMemorySize, GSMEM);
    cudaFuncSetAttribute(attn_kernel,     cudaFuncAttributeMaxDynamicSharedMemorySize, AT_SMEM);

    // 1) transpose + split all 8 weight matrices -> Wt[n][k] fp16 hi/lo
    transpose_split_kernel<<<dim3(Dm / 32, Cm / 32, 8), 256>>>(
        Wq, Wo, Wk, Wv, Wk_id, Wv_id, Wk_h, Wv_h);

    // 2) activations -> single fp16
    split_inputs_kernel<<<dim3(8192, 1, 4), 256>>>(hidden, text, ids, hair);

    // 3) Q GEMM + all six K/V projections in ONE launch (2-pass fp16, 3-stage)
    gemm_qkv_kernel<<<dim3(Dm / BN, 256 + 14), 256, GSMEM>>>();

    // 4) flash-style MMA attention (3-pass fp16) -> g_O16
    attn_kernel<<<dim3(Sq / 128, Bsz * Hh), 256, AT_SMEM>>>();

    // 5) out = O @ Wo + bo (2-pass fp16, 3-stage)
    gemm_out_kernel<<<dim3(Dm / BN, Mbig / BM), 256, GSMEM>>>(bo, out);
}

// round 15
// speedup vs baseline: 1.5263x; 1.5263x over previous
#include <cuda_runtime.h>
#include <cuda_bf16.h>
#include <cstdint>

// ---------------------------------------------------------------------------
// Problem constants
// ---------------------------------------------------------------------------
#define Bsz  8
#define Sq   4096
#define Ltxt 77
#define Limg 16
#define Dm   1280
#define Cm   2048
#define Hh   20
#define DHd  64
#define Mbig (Bsz * Sq)          // 32768
#define Mtxt (Bsz * Ltxt)        // 616
#define Mimg (Bsz * Limg)        // 128

// ---------------------------------------------------------------------------
// Scratch (__device__ globals; no allocation allowed)
// ---------------------------------------------------------------------------
// tf32-rounded fp32 activations (A operands of 1-pass tf32 GEMMs)
__device__ float g_A32[(size_t)Mbig * Dm];
__device__ float g_O32[(size_t)Mbig * Dm];
__device__ float g_T32[(size_t)Mtxt * Cm];
__device__ float g_I32[(size_t)Mimg * Cm];
__device__ float g_H32[(size_t)Mimg * Cm];

// Q and K/V as bf16 hi/lo (attention runs 3-pass bf16 — the fast HMMA flavor)
__device__ __nv_bfloat16 g_Qhi[(size_t)Mbig * Dm], g_Qlo[(size_t)Mbig * Dm];
// z: 0 Ktxt, 1 Vtxt, 2 Kid, 3 Vid, 4 Khair, 5 Vhair
__device__ __nv_bfloat16 g_KVhi[6][(size_t)Mtxt * Dm];
__device__ __nv_bfloat16 g_KVlo[6][(size_t)Mtxt * Dm];

// transposed tf32-rounded weights: Wt[n][k] fp32 (B operands)
__device__ float g_WtQ[(size_t)Dm * Dm];
__device__ float g_WtO[(size_t)Dm * Dm];
__device__ float g_WtKV[6][(size_t)Dm * Cm];

// ---------------------------------------------------------------------------
// Helpers
// ---------------------------------------------------------------------------
__device__ __forceinline__ uint32_t smem_u32(const void* p) {
    uint32_t a;
    asm("{ .reg .u64 t; cvta.to.shared.u64 t, %1; cvt.u32.u64 %0, t; }"
        : "=r"(a) : "l"(p));
    return a;
}
__device__ __forceinline__ float rna_tf32(float v) {
    uint32_t r;
    asm("cvt.rna.tf32.f32 %0, %1;" : "=r"(r) : "f"(v));
    return __uint_as_float(r);
}
__device__ __forceinline__ void split1(float v, __nv_bfloat16& h, __nv_bfloat16& l) {
    h = __float2bfloat16_rn(v);
    l = __float2bfloat16_rn(v - __bfloat162float(h));
}
// two floats -> packed bf16x2 hi + packed bf16x2 lo
__device__ __forceinline__ void sp2(float v0, float v1, uint32_t& h, uint32_t& l) {
    __nv_bfloat16 b0 = __float2bfloat16_rn(v0);
    __nv_bfloat16 b1 = __float2bfloat16_rn(v1);
    __nv_bfloat162 hh = __halves2bfloat162(b0, b1);
    h = *(uint32_t*)&hh;
    __nv_bfloat162 ll = __halves2bfloat162(
        __float2bfloat16_rn(v0 - __bfloat162float(b0)),
        __float2bfloat16_rn(v1 - __bfloat162float(b1)));
    l = *(uint32_t*)&ll;
}
__device__ __forceinline__ void cpa16(uint32_t dst, const void* src, bool p) {
    int sz = p ? 16 : 0;
    asm volatile("cp.async.cg.shared.global [%0], [%1], 16, %2;"
                 :: "r"(dst), "l"(src), "r"(sz));
}
__device__ __forceinline__ void ldm4(uint32_t* r, uint32_t addr) {
    asm volatile("ldmatrix.sync.aligned.m8n8.x4.shared.b16 {%0,%1,%2,%3}, [%4];"
                 : "=r"(r[0]), "=r"(r[1]), "=r"(r[2]), "=r"(r[3]) : "r"(addr));
}
__device__ __forceinline__ void ldm4t(uint32_t* r, uint32_t addr) {
    asm volatile("ldmatrix.sync.aligned.m8n8.x4.trans.shared.b16 {%0,%1,%2,%3}, [%4];"
                 : "=r"(r[0]), "=r"(r[1]), "=r"(r[2]), "=r"(r[3]) : "r"(addr));
}
// bf16 HMMA (attention)
__device__ __forceinline__ void mma16816(float* d, const uint32_t* a,
                                         uint32_t b0, uint32_t b1) {
    asm volatile(
        "mma.sync.aligned.m16n8k16.row.col.f32.bf16.bf16.f32 "
        "{%0,%1,%2,%3}, {%4,%5,%6,%7}, {%8,%9}, {%0,%1,%2,%3};"
        : "+f"(d[0]), "+f"(d[1]), "+f"(d[2]), "+f"(d[3])
        : "r"(a[0]), "r"(a[1]), "r"(a[2]), "r"(a[3]), "r"(b0), "r"(b1));
}
// tf32 mma (GEMMs)
__device__ __forceinline__ void mma_tf32(float* d, const uint32_t* a,
                                         uint32_t b0, uint32_t b1) {
    asm volatile(
        "mma.sync.aligned.m16n8k8.row.col.f32.tf32.tf32.f32 "
        "{%0,%1,%2,%3}, {%4,%5,%6,%7}, {%8,%9}, {%0,%1,%2,%3};"
        : "+f"(d[0]), "+f"(d[1]), "+f"(d[2]), "+f"(d[3])
        : "r"(a[0]), "r"(a[1]), "r"(a[2]), "r"(a[3]), "r"(b0), "r"(b1));
}

// ---------------------------------------------------------------------------
// Weight transpose + tf32 rounding:  W[K,N=1280] fp32 -> Wt[N,K] fp32 (rna)
// ---------------------------------------------------------------------------
__global__ void __launch_bounds__(256)
transpose_w_kernel(const float* __restrict__ Wq, const float* __restrict__ Wo,
                   const float* __restrict__ Wk,  const float* __restrict__ Wv,
                   const float* __restrict__ Wki, const float* __restrict__ Wvi,
                   const float* __restrict__ Wkh, const float* __restrict__ Wvh) {
    const float* W; float* Wt; int K;
    switch (blockIdx.z) {
        case 0: W = Wq;  Wt = g_WtQ;     K = Dm; break;
        case 1: W = Wo;  Wt = g_WtO;     K = Dm; break;
        case 2: W = Wk;  Wt = g_WtKV[0]; K = Cm; break;
        case 3: W = Wv;  Wt = g_WtKV[1]; K = Cm; break;
        case 4: W = Wki; Wt = g_WtKV[2]; K = Cm; break;
        case 5: W = Wvi; Wt = g_WtKV[3]; K = Cm; break;
        case 6: W = Wkh; Wt = g_WtKV[4]; K = Cm; break;
        default:W = Wvh; Wt = g_WtKV[5]; K = Cm; break;
    }
    int k0 = blockIdx.y * 32;
    if (k0 >= K) return;
    int n0 = blockIdx.x * 32;

    __shared__ float ts[32][33];
    int tx = threadIdx.x & 31;
    int ty = threadIdx.x >> 5;
#pragma unroll
    for (int j = 0; j < 4; j++)
        ts[ty + j * 8][tx] = W[(size_t)(k0 + ty + j * 8) * Dm + n0 + tx];
    __syncthreads();
#pragma unroll
    for (int j = 0; j < 4; j++) {
        int nn = ty + j * 8;
        Wt[(size_t)(n0 + nn) * K + k0 + tx] = rna_tf32(ts[tx][nn]);
    }
}

// ---------------------------------------------------------------------------
// Activation rounding: fp32 -> tf32-rounded fp32 (RN semantics in mma)
// ---------------------------------------------------------------------------
__global__ void __launch_bounds__(256)
cvt_inputs_kernel(const float* __restrict__ hidden, const float* __restrict__ text,
                  const float* __restrict__ ids,    const float* __restrict__ hair) {
    const float* src; float* dst; size_t n;
    switch (blockIdx.z) {
        case 0:  src = hidden; dst = g_A32; n = (size_t)Mbig * Dm; break;
        case 1:  src = text;   dst = g_T32; n = (size_t)Mtxt * Cm; break;
        case 2:  src = ids;    dst = g_I32; n = (size_t)Mimg * Cm; break;
        default: src = hair;   dst = g_H32; n = (size_t)Mimg * Cm; break;
    }
    size_t n4 = n >> 2;
    for (size_t i = (size_t)blockIdx.x * 256 + threadIdx.x; i < n4;
         i += (size_t)gridDim.x * 256) {
        float4 v = ((const float4*)src)[i];
        float4 o;
        o.x = rna_tf32(v.x); o.y = rna_tf32(v.y);
        o.z = rna_tf32(v.z); o.w = rna_tf32(v.w);
        ((float4*)dst)[i] = o;
    }
}

// ---------------------------------------------------------------------------
// tf32 single-pass GEMM: C[M,1280] = A[M,K] @ Wt[1280,K]^T, both tf32-rounded.
// 128x128 tile, BK=32, 8 warps (64x32 each), 2-stage cp.async.
// Fragments via conflict-free scalar LDS (row stride 36 floats).
// ---------------------------------------------------------------------------
#define BM 128
#define BN 128
#define BKB 32
#define RSTR 36                  // floats per smem row (32 data + 4 pad)
#define ROWBYTES 144
#define A_OFF 0
#define B_OFF 18432              // 128*144
#define STAGE_B 36864
#define NSTAGE 2
#define GSMEM (NSTAGE * STAGE_B) // 73728

__device__ __forceinline__ void tf32_gemm_body(
    const float* __restrict__ A, const float* __restrict__ Bt,
    const float* __restrict__ bias,
    float* __restrict__ Cf,
    __nv_bfloat16* __restrict__ Chi, __nv_bfloat16* __restrict__ Clo,
    int M, int K, int bx, int by)
{
    extern __shared__ __align__(128) char smem[];
    const int tid  = threadIdx.x;
    const int lane = tid & 31;
    const int wid  = tid >> 5;
    const int wm   = wid & 1;
    const int wn   = wid >> 1;
    const int row0 = by * BM;
    const int col0 = bx * BN;
    const int nch  = K / BKB;
    const int tg   = lane >> 2;
    const int tq   = lane & 3;

    float acc[4][4][4];
#pragma unroll
    for (int a = 0; a < 4; a++)
#pragma unroll
        for (int b = 0; b < 4; b++)
#pragma unroll
            for (int d = 0; d < 4; d++) acc[a][b][d] = 0.f;

    // FIXED loader: 128 rows x 8 x 16B segments = 1024 cp.async per operand
    auto ld_stage = [&](int c, int s) {
        uint32_t base = smem_u32(smem + s * STAGE_B);
        int k0 = c * BKB;
#pragma unroll
        for (int i = 0; i < 4; i++) {
            int lin = i * 256 + tid;       // 0..1023
            int r   = lin >> 3;            // row 0..127
            int sg  = lin & 7;             // 16B segment (4 floats), 0..7
            int grow = row0 + r;
            bool p = grow < M;
            int ga = p ? grow : (M - 1);
            cpa16(base + A_OFF + r * ROWBYTES + sg * 16,
                  A + (size_t)ga * K + k0 + sg * 4, p);
            cpa16(base + B_OFF + r * ROWBYTES + sg * 16,
                  Bt + (size_t)(col0 + r) * K + k0 + sg * 4, true);
        }
        asm volatile("cp.async.commit_group;" ::: "memory");
    };

    auto compute = [&](int s) {
        const float* As = (const float*)(smem + s * STAGE_B + A_OFF);
        const float* Bs = (const float*)(smem + s * STAGE_B + B_OFF);
#pragma unroll
        for (int ks = 0; ks < 4; ks++) {
            uint32_t bfr[4][2];
#pragma unroll
            for (int n8 = 0; n8 < 4; n8++) {
                const float* bp = Bs + (wn * 32 + n8 * 8 + tg) * RSTR + ks * 8 + tq;
                bfr[n8][0] = __float_as_uint(bp[0]);
                bfr[n8][1] = __float_as_uint(bp[4]);
            }
#pragma unroll
            for (int mt = 0; mt < 4; mt++) {
                const float* ap = As + (wm * 64 + mt * 16 + tg) * RSTR + ks * 8 + tq;
                uint32_t a[4];
                a[0] = __float_as_uint(ap[0]);
                a[1] = __float_as_uint(ap[8 * RSTR]);
                a[2] = __float_as_uint(ap[4]);
                a[3] = __float_as_uint(ap[8 * RSTR + 4]);
#pragma unroll
                for (int n8 = 0; n8 < 4; n8++)
                    mma_tf32(acc[mt][n8], a, bfr[n8][0], bfr[n8][1]);
            }
        }
    };

    ld_stage(0, 0);
    for (int c = 0; c < nch; c++) {
        int s = c & 1;
        if (c + 1 < nch) {
            ld_stage(c + 1, s ^ 1);
            asm volatile("cp.async.wait_group 1;" ::: "memory");
        } else {
            asm volatile("cp.async.wait_group 0;" ::: "memory");
        }
        __syncthreads();
        compute(s);
        __syncthreads();
    }

    // epilogue: D rows tg/tg+8, cols 2tq,2tq+1 within each (mt, n8) tile
#pragma unroll
    for (int mt = 0; mt < 4; mt++) {
        int r0 = row0 + wm * 64 + mt * 16 + tg;
        int r1 = r0 + 8;
#pragma unroll
        for (int n8 = 0; n8 < 4; n8++) {
            int col = col0 + wn * 32 + n8 * 8 + tq * 2;
            if (Cf) {
                float b0 = 0.f, b1 = 0.f;
                if (bias) { b0 = bias[col]; b1 = bias[col + 1]; }
                if (r0 < M)
                    *(float2*)(Cf + (size_t)r0 * Dm + col) =
                        make_float2(acc[mt][n8][0] + b0, acc[mt][n8][1] + b1);
                if (r1 < M)
                    *(float2*)(Cf + (size_t)r1 * Dm + col) =
                        make_float2(acc[mt][n8][2] + b0, acc[mt][n8][3] + b1);
            } else {
                uint32_t h, l;
                if (r0 < M) {
                    sp2(acc[mt][n8][0], acc[mt][n8][1], h, l);
                    *(uint32_t*)(Chi + (size_t)r0 * Dm + col) = h;
                    *(uint32_t*)(Clo + (size_t)r0 * Dm + col) = l;
                }
                if (r1 < M) {
                    sp2(acc[mt][n8][2], acc[mt][n8][3], h, l);
                    *(uint32_t*)(Chi + (size_t)r1 * Dm + col) = h;
                    *(uint32_t*)(Clo + (size_t)r1 * Dm + col) = l;
                }
            }
        }
    }
}

// Merged Q + 6xKV GEMM (split bf16 outputs for bf16 attention)
__global__ void __launch_bounds__(256, 2)
gemm_qkv_kernel() {
    int y = blockIdx.y;
    if (y < 256) {
        tf32_gemm_body(g_A32, g_WtQ, nullptr,
                       nullptr, g_Qhi, g_Qlo, Mbig, Dm, blockIdx.x, y);
        return;
    }
    int yy = y - 256;
    const float* a32; int M, z, by;
    if (yy < 5)       { z = 0; by = yy;     a32 = g_T32; M = Mtxt; }
    else if (yy < 10) { z = 1; by = yy - 5; a32 = g_T32; M = Mtxt; }
    else if (yy == 10){ z = 2; by = 0;      a32 = g_I32; M = Mimg; }
    else if (yy == 11){ z = 3; by = 0;      a32 = g_I32; M = Mimg; }
    else if (yy == 12){ z = 4; by = 0;      a32 = g_H32; M = Mimg; }
    else              { z = 5; by = 0;      a32 = g_H32; M = Mimg; }
    tf32_gemm_body(a32, g_WtKV[z], nullptr,
                   nullptr, g_KVhi[z], g_KVlo[z], M, Cm, blockIdx.x, by);
}

__global__ void __launch_bounds__(256, 2)
gemm_out_kernel(const float* __restrict__ bo, float* __restrict__ out) {
    tf32_gemm_body(g_O32, g_WtO, bo,
                   out, nullptr, nullptr, Mbig, Dm, blockIdx.x, blockIdx.y);
}

// ---------------------------------------------------------------------------
// Flash-style MMA attention (bf16 3-pass — the fast HMMA flavor; R8-proven).
// Block = 128 q x one (b,h). Epilogue writes tf32-rounded fp32 O.
// ---------------------------------------------------------------------------
#define AT_QHI 0
#define AT_QLO 18432
#define AT_KHI 36864
#define AT_KLO 48384
#define AT_SMEM 59904
#define KROW 144                 // SMEM row stride bytes (64 bf16 + 8 pad)

__global__ void __launch_bounds__(256) attn_kernel() {
    extern __shared__ __align__(128) char sm[];
    const int tid  = threadIdx.x;
    const int lane = tid & 31;
    const int wid  = tid >> 5;
    const int lrow = lane & 15;
    const int lhalf = (lane >> 4) * 16;
    const int tg = lane >> 2;
    const int tq = lane & 3;
    const int q0 = blockIdx.x * 128;
    const int b  = blockIdx.y / Hh;
    const int hd = blockIdx.y % Hh;
    const int wq0 = wid * 16;

    const uint32_t smb = smem_u32(sm);

    // ---- stage Q hi/lo [128 x 64] ----
    for (int i = tid; i < 1024; i += 256) {
        int row = i >> 3, seg = i & 7;
        size_t off = ((size_t)(b * Sq + q0 + row)) * Dm + hd * 64 + seg * 8;
        *(uint4*)(sm + AT_QHI + row * KROW + seg * 16) = *(const uint4*)(g_Qhi + off);
        *(uint4*)(sm + AT_QLO + row * KROW + seg * 16) = *(const uint4*)(g_Qlo + off);
    }
    __syncthreads();

    uint32_t qh[4][4], ql[4][4];
#pragma unroll
    for (int ks = 0; ks < 4; ks++) {
        uint32_t ad = smb + AT_QHI + (wq0 + lrow) * KROW + ks * 32 + lhalf;
        ldm4(qh[ks], ad);
        ldm4(ql[ks], ad + (AT_QLO - AT_QHI));
    }

    float O[8][4];
#pragma unroll
    for (int i = 0; i < 8; i++)
#pragma unroll
        for (int e = 0; e < 4; e++) O[i][e] = 0.f;

    // ======================= branch 0: text (77 j, pad 80) =======================
    {
        for (int i = tid; i < 640; i += 256) {
            int row = i >> 3, seg = i & 7;
            uint4 vh = make_uint4(0, 0, 0, 0), vl = vh;
            if (row < Ltxt) {
                size_t off = ((size_t)(b * Ltxt + row)) * Dm + hd * 64 + seg * 8;
                vh = *(const uint4*)(g_KVhi[0] + off);
                vl = *(const uint4*)(g_KVlo[0] + off);
            }
            *(uint4*)(sm + AT_KHI + row * KROW + seg * 16) = vh;
            *(uint4*)(sm + AT_KLO + row * KROW + seg * 16) = vl;
        }
        __syncthreads();

        float S[10][4];
#pragma unroll
        for (int t = 0; t < 10; t++)
#pragma unroll
            for (int e = 0; e < 4; e++) S[t][e] = 0.f;

#pragma unroll
        for (int np = 0; np < 5; np++)
#pragma unroll
            for (int ks = 0; ks < 4; ks++) {
                uint32_t bh[4], bl[4];
                uint32_t ad = smb + AT_KHI + (np * 16 + lrow) * KROW + ks * 32 + lhalf;
                ldm4(bh, ad);
                ldm4(bl, ad + (AT_KLO - AT_KHI));
#pragma unroll
                for (int q = 0; q < 2; q++) {
                    int t = np * 2 + q;
                    mma16816(S[t], qh[ks], bh[q], bh[q + 2]);
                    mma16816(S[t], qh[ks], bl[q], bl[q + 2]);
                    mma16816(S[t], ql[ks], bh[q], bh[q + 2]);
                }
            }

#pragma unroll
        for (int t = 0; t < 10; t++)
#pragma unroll
            for (int e = 0; e < 4; e++) S[t][e] *= 0.125f;
        if (tq == 3) { S[9][0] = -1e30f; S[9][2] = -1e30f; }
        if (tq >= 2) { S[9][1] = -1e30f; S[9][3] = -1e30f; }

        float mx0 = -1e30f, mx1 = -1e30f;
#pragma unroll
        for (int t = 0; t < 10; t++) {
            mx0 = fmaxf(mx0, fmaxf(S[t][0], S[t][1]));
            mx1 = fmaxf(mx1, fmaxf(S[t][2], S[t][3]));
        }
        mx0 = fmaxf(mx0, __shfl_xor_sync(0xffffffffu, mx0, 1));
        mx0 = fmaxf(mx0, __shfl_xor_sync(0xffffffffu, mx0, 2));
        mx1 = fmaxf(mx1, __shfl_xor_sync(0xffffffffu, mx1, 1));
        mx1 = fmaxf(mx1, __shfl_xor_sync(0xffffffffu, mx1, 2));
        float s0 = 0.f, s1 = 0.f;
#pragma unroll
        for (int t = 0; t < 10; t++) {
            S[t][0] = __expf(S[t][0] - mx0); S[t][1] = __expf(S[t][1] - mx0);
            S[t][2] = __expf(S[t][2] - mx1); S[t][3] = __expf(S[t][3] - mx1);
            s0 += S[t][0] + S[t][1];
            s1 += S[t][2] + S[t][3];
        }
        s0 += __shfl_xor_sync(0xffffffffu, s0, 1);
        s0 += __shfl_xor_sync(0xffffffffu, s0, 2);
        s1 += __shfl_xor_sync(0xffffffffu, s1, 1);
        s1 += __shfl_xor_sync(0xffffffffu, s1, 2);
        float inv0 = 1.f / s0, inv1 = 1.f / s1;

        uint32_t phi[5][4], plo[5][4];
#pragma unroll
        for (int kj = 0; kj < 5; kj++) {
            int t0 = 2 * kj, t1 = 2 * kj + 1;
            sp2(S[t0][0] * inv0, S[t0][1] * inv0, phi[kj][0], plo[kj][0]);
            sp2(S[t0][2] * inv1, S[t0][3] * inv1, phi[kj][1], plo[kj][1]);
            sp2(S[t1][0] * inv0, S[t1][1] * inv0, phi[kj][2], plo[kj][2]);
            sp2(S[t1][2] * inv1, S[t1][3] * inv1, phi[kj][3], plo[kj][3]);
        }
        __syncthreads();

        for (int i = tid; i < 640; i += 256) {
            int row = i >> 3, seg = i & 7;
            uint4 vh = make_uint4(0, 0, 0, 0), vl = vh;
            if (row < Ltxt) {
                size_t off = ((size_t)(b * Ltxt + row)) * Dm + hd * 64 + seg * 8;
                vh = *(const uint4*)(g_KVhi[1] + off);
                vl = *(const uint4*)(g_KVlo[1] + off);
            }
            *(uint4*)(sm + AT_KHI + row * KROW + seg * 16) = vh;
            *(uint4*)(sm + AT_KLO + row * KROW + seg * 16) = vl;
        }
        __syncthreads();

#pragma unroll
        for (int kj = 0; kj < 5; kj++) {
            int vrow = kj * 16 + ((lane >> 3) & 1) * 8 + (lane & 7);
#pragma unroll
            for (int ndp = 0; ndp < 4; ndp++) {
                uint32_t vh[4], vl[4];
                uint32_t ad = smb + AT_KHI + vrow * KROW +
                              (ndp * 2 + (lane >> 4)) * 16;
                ldm4t(vh, ad);
                ldm4t(vl, ad + (AT_KLO - AT_KHI));
                mma16816(O[ndp * 2],     phi[kj], vh[0], vh[1]);
                mma16816(O[ndp * 2],     phi[kj], vl[0], vl[1]);
                mma16816(O[ndp * 2],     plo[kj], vh[0], vh[1]);
                mma16816(O[ndp * 2 + 1], phi[kj], vh[2], vh[3]);
                mma16816(O[ndp * 2 + 1], phi[kj], vl[2], vl[3]);
                mma16816(O[ndp * 2 + 1], plo[kj], vh[2], vh[3]);
            }
        }
        __syncthreads();
    }

    // =============== branch 1: merged id (j 0-15) | hair (j 16-31) ===============
    {
        {
            int i = tid;
            int row = i >> 3, seg = i & 7;
            int src_z = (row < 16) ? 2 : 4;
            int r = (row < 16) ? row : row - 16;
            size_t off = ((size_t)(b * Limg + r)) * Dm + hd * 64 + seg * 8;
            *(uint4*)(sm + AT_KHI + row * KROW + seg * 16) =
                *(const uint4*)(g_KVhi[src_z] + off);
            *(uint4*)(sm + AT_KLO + row * KROW + seg * 16) =
                *(const uint4*)(g_KVlo[src_z] + off);
        }
        __syncthreads();

        float S[4][4];
#pragma unroll
        for (int t = 0; t < 4; t++)
#pragma unroll
            for (int e = 0; e < 4; e++) S[t][e] = 0.f;

#pragma unroll
        for (int np = 0; np < 2; np++)
#pragma unroll
            for (int ks = 0; ks < 4; ks++) {
                uint32_t bh[4], bl[4];
                uint32_t ad = smb + AT_KHI + (np * 16 + lrow) * KROW + ks * 32 + lhalf;
                ldm4(bh, ad);
                ldm4(bl, ad + (AT_KLO - AT_KHI));
#pragma unroll
                for (int q = 0; q < 2; q++) {
                    int t = np * 2 + q;
                    mma16816(S[t], qh[ks], bh[q], bh[q + 2]);
                    mma16816(S[t], qh[ks], bl[q], bl[q + 2]);
                    mma16816(S[t], ql[ks], bh[q], bh[q + 2]);
                }
            }

#pragma unroll
        for (int t = 0; t < 4; t++)
#pragma unroll
            for (int e = 0; e < 4; e++) S[t][e] *= 0.125f;

        uint32_t phi[2][4], plo[2][4];
#pragma unroll
        for (int hf = 0; hf < 2; hf++) {
            int ta = 2 * hf, tb = 2 * hf + 1;
            float mx0 = fmaxf(fmaxf(S[ta][0], S[ta][1]), fmaxf(S[tb][0], S[tb][1]));
            float mx1 = fmaxf(fmaxf(S[ta][2], S[ta][3]), fmaxf(S[tb][2], S[tb][3]));
            mx0 = fmaxf(mx0, __shfl_xor_sync(0xffffffffu, mx0, 1));
            mx0 = fmaxf(mx0, __shfl_xor_sync(0xffffffffu, mx0, 2));
            mx1 = fmaxf(mx1, __shfl_xor_sync(0xffffffffu, mx1, 1));
            mx1 = fmaxf(mx1, __shfl_xor_sync(0xffffffffu, mx1, 2));
            float e00 = __expf(S[ta][0] - mx0), e01 = __expf(S[ta][1] - mx0);
            float e02 = __expf(S[ta][2] - mx1), e03 = __expf(S[ta][3] - mx1);
            float e10 = __expf(S[tb][0] - mx0), e11 = __expf(S[tb][1] - mx0);
            float e12 = __expf(S[tb][2] - mx1), e13 = __expf(S[tb][3] - mx1);
            float s0 = e00 + e01 + e10 + e11;
            float s1 = e02 + e03 + e12 + e13;
            s0 += __shfl_xor_sync(0xffffffffu, s0, 1);
            s0 += __shfl_xor_sync(0xffffffffu, s0, 2);
            s1 += __shfl_xor_sync(0xffffffffu, s1, 1);
            s1 += __shfl_xor_sync(0xffffffffu, s1, 2);
            float inv0 = 1.f / s0, inv1 = 1.f / s1;
            sp2(e00 * inv0, e01 * inv0, phi[hf][0], plo[hf][0]);
            sp2(e02 * inv1, e03 * inv1, phi[hf][1], plo[hf][1]);
            sp2(e10 * inv0, e11 * inv0, phi[hf][2], plo[hf][2]);
            sp2(e12 * inv1, e13 * inv1, phi[hf][3], plo[hf][3]);
        }
        __syncthreads();

        {
            int i = tid;
            int row = i >> 3, seg = i & 7;
            int src_z = (row < 16) ? 3 : 5;
            int r = (row < 16) ? row : row - 16;
            size_t off = ((size_t)(b * Limg + r)) * Dm + hd * 64 + seg * 8;
            *(uint4*)(sm + AT_KHI + row * KROW + seg * 16) =
                *(const uint4*)(g_KVhi[src_z] + off);
            *(uint4*)(sm + AT_KLO + row * KROW + seg * 16) =
                *(const uint4*)(g_KVlo[src_z] + off);
        }
        __syncthreads();

#pragma unroll
        for (int kj = 0; kj < 2; kj++) {
            int vrow = kj * 16 + ((lane >> 3) & 1) * 8 + (lane & 7);
#pragma unroll
            for (int ndp = 0; ndp < 4; ndp++) {
                uint32_t vh[4], vl[4];
                uint32_t ad = smb + AT_KHI + vrow * KROW +
                              (ndp * 2 + (lane >> 4)) * 16;
                ldm4t(vh, ad);
                ldm4t(vl, ad + (AT_KLO - AT_KHI));
                mma16816(O[ndp * 2],     phi[kj], vh[0], vh[1]);
                mma16816(O[ndp * 2],     phi[kj], vl[0], vl[1]);
                mma16816(O[ndp * 2],     plo[kj], vh[0], vh[1]);
                mma16816(O[ndp * 2 + 1], phi[kj], vh[2], vh[3]);
                mma16816(O[ndp * 2 + 1], phi[kj], vl[2], vl[3]);
                mma16816(O[ndp * 2 + 1], plo[kj], vh[2], vh[3]);
            }
        }
    }

    // ---- epilogue: tf32-rounded fp32 O (out-GEMM A operand) ----
    {
        size_t r0 = (size_t)(b * Sq + q0 + wq0 + tg) * Dm + hd * 64 + tq * 2;
        size_t r1 = r0 + 8 * (size_t)Dm;
#pragma unroll
        for (int nd = 0; nd < 8; nd++) {
            *(float2*)(g_O32 + r0 + nd * 8) =
                make_float2(rna_tf32(O[nd][0]), rna_tf32(O[nd][1]));
            *(float2*)(g_O32 + r1 + nd * 8) =
                make_float2(rna_tf32(O[nd][2]), rna_tf32(O[nd][3]));
        }
    }
}

// ---------------------------------------------------------------------------
// kernel_launch
// ---------------------------------------------------------------------------
extern "C" void kernel_launch(void* const* d_in, const int* in_sizes, int n_in,
                              void* d_out, int out_size) {
    const float* hidden = (const float*)d_in[0];
    const float* text   = (const float*)d_in[1];
    const float* ids    = (const float*)d_in[2];
    const float* hair   = (const float*)d_in[3];
    const float* Wq     = (const float*)d_in[4];
    const float* Wk     = (const float*)d_in[5];
    const float* Wv     = (const float*)d_in[6];
    const float* Wo     = (const float*)d_in[7];
    const float* bo     = (const float*)d_in[8];
    const float* Wk_id  = (const float*)d_in[9];
    const float* Wv_id  = (const float*)d_in[10];
    const float* Wk_h   = (const float*)d_in[11];
    const float* Wv_h   = (const float*)d_in[12];
    float* out = (float*)d_out;

    cudaFuncSetAttribute(gemm_qkv_kernel, cudaFuncAttributeMaxDynamicSharedMemorySize, GSMEM);
    cudaFuncSetAttribute(gemm_out_kernel, cudaFuncAttributeMaxDynamicSharedMemorySize, GSMEM);
    cudaFuncSetAttribute(attn_kernel,     cudaFuncAttributeMaxDynamicSharedMemorySize, AT_SMEM);

    // 1) transpose + tf32-round all 8 weight matrices -> Wt[n][k] fp32
    transpose_w_kernel<<<dim3(Dm / 32, Cm / 32, 8), 256>>>(
        Wq, Wo, Wk, Wv, Wk_id, Wv_id, Wk_h, Wv_h);

    // 2) tf32-round activations (RN instead of HW truncation)
    cvt_inputs_kernel<<<dim3(4096, 1, 4), 256>>>(hidden, text, ids, hair);

    // 3) Q GEMM + all six K/V projections, single-pass tf32
    gemm_qkv_kernel<<<dim3(Dm / BN, 256 + 14), 256, GSMEM>>>();

    // 4) flash-style bf16 MMA attention -> g_O32 (tf32-rounded)
    attn_kernel<<<dim3(Sq / 128, Bsz * Hh), 256, AT_SMEM>>>();

    // 5) out = O @ Wo + bo, single-pass tf32
    gemm_out_kernel<<<dim3(Dm / BN, Mbig / BM), 256, GSMEM>>>(bo, out);
}